// round 9
// baseline (speedup 1.0000x reference)
#include <cuda_runtime.h>
#include <cuda_fp16.h>
#include <cuda_bf16.h>
#include <cstdint>
#include <cstring>

#define NN 100000
#define NE 800000
#define DM 128

typedef unsigned long long u64;

__device__ __forceinline__ uint32_t smem_to_u32(const void* p) {
    uint32_t a;
    asm("{ .reg .u64 t; cvta.to.shared.u64 t, %1; cvt.u32.u64 %0, t; }" : "=r"(a) : "l"(p));
    return a;
}
__device__ __forceinline__ uint32_t h2_to_u32(__half2 h) {
    uint32_t u;
    memcpy(&u, &h, 4);
    return u;
}
__device__ __forceinline__ void ldsm4(uint32_t* r, uint32_t addr) {
    asm volatile("ldmatrix.sync.aligned.m8n8.x4.shared.b16 {%0,%1,%2,%3}, [%4];"
        : "=r"(r[0]), "=r"(r[1]), "=r"(r[2]), "=r"(r[3]) : "r"(addr));
}
__device__ __forceinline__ void mma16816(float* c, const uint32_t* a, const uint32_t* b) {
    asm volatile(
        "mma.sync.aligned.m16n8k16.row.col.f32.f16.f16.f32 "
        "{%0,%1,%2,%3}, {%4,%5,%6,%7}, {%8,%9}, {%0,%1,%2,%3};"
        : "+f"(c[0]), "+f"(c[1]), "+f"(c[2]), "+f"(c[3])
        : "r"(a[0]), "r"(a[1]), "r"(a[2]), "r"(a[3]), "r"(b[0]), "r"(b[1]));
}

// ---------------- scratch (device globals: no cudaMalloc allowed) ----------------
__device__ float  g_deg[NN];
__device__ float  g_dis[NN];
__device__ int    g_cnt[NN];
__device__ int    g_off[NN + 1];
__device__ int    g_cur[NN];
__device__ int    g_src[2 * NE];
__device__ float  g_w[2 * NE];
__device__ __half g_aggh[(size_t)NN * DM];   // aggregation result, fp16 (A of GEMM)
__device__ float  g_buf1[(size_t)NN * DM];
__device__ __half g_xh[(size_t)NN * DM];     // node features fp16 (gather table)
__device__ __half g_wt[DM * DM];             // W^T fp16, [n][k] row-major

#define SCB 256
#define SNB ((NN + SCB - 1) / SCB)   // 391 scan blocks
__device__ int g_bsum[SNB];
__device__ int g_boff[SNB];

// ---------------- build kernels ----------------
__global__ void k_zero() {
    int i = blockIdx.x * blockDim.x + threadIdx.x;
    if (i < NN) { g_deg[i] = 0.f; g_cnt[i] = 0; }
}

__global__ void k_deg(const int* __restrict__ s, const int* __restrict__ r,
                      const float* __restrict__ e) {
    int i = blockIdx.x * blockDim.x + threadIdx.x;
    if (i < NE) {
        int a = s[i], b = r[i];
        float ev = e[i];
        atomicAdd(&g_deg[a], ev);
        atomicAdd(&g_deg[b], ev);
        atomicAdd(&g_cnt[a], 1);
        atomicAdd(&g_cnt[b], 1);
    }
}

__global__ void k_dis() {
    int i = blockIdx.x * blockDim.x + threadIdx.x;
    if (i < NN) {
        float d = g_deg[i];
        g_dis[i] = (d > 0.f) ? rsqrtf(d) : 0.f;
    }
}

__global__ void k_scan1() {
    __shared__ int sh[SCB];
    int i = blockIdx.x * SCB + threadIdx.x;
    int v = (i < NN) ? g_cnt[i] : 0;
    sh[threadIdx.x] = v;
    __syncthreads();
    for (int d = SCB / 2; d > 0; d >>= 1) {
        if (threadIdx.x < d) sh[threadIdx.x] += sh[threadIdx.x + d];
        __syncthreads();
    }
    if (threadIdx.x == 0) g_bsum[blockIdx.x] = sh[0];
}

__global__ void k_scan2() {
    __shared__ int sh[512];
    int t = threadIdx.x;
    int v = (t < SNB) ? g_bsum[t] : 0;
    sh[t] = v;
    __syncthreads();
    for (int d = 1; d < 512; d <<= 1) {
        int x = 0;
        if (t >= d) x = sh[t - d];
        __syncthreads();
        sh[t] += x;
        __syncthreads();
    }
    if (t < SNB) g_boff[t] = sh[t] - v;
    if (t == SNB - 1) g_off[NN] = sh[t];
}

__global__ void k_scan3() {
    __shared__ int sh[SCB];
    int i = blockIdx.x * SCB + threadIdx.x;
    int t = threadIdx.x;
    int v = (i < NN) ? g_cnt[i] : 0;
    sh[t] = v;
    __syncthreads();
    for (int d = 1; d < SCB; d <<= 1) {
        int x = 0;
        if (t >= d) x = sh[t - d];
        __syncthreads();
        sh[t] += x;
        __syncthreads();
    }
    if (i < NN) {
        int excl = sh[t] - v + g_boff[blockIdx.x];
        g_off[i] = excl;
        g_cur[i] = excl;
    }
}

__global__ void k_fill(const int* __restrict__ s, const int* __restrict__ r,
                       const float* __restrict__ e) {
    int i = blockIdx.x * blockDim.x + threadIdx.x;
    if (i < NE) {
        int a = s[i], b = r[i];
        float w = g_dis[a] * e[i] * g_dis[b];
        int p = atomicAdd(&g_cur[b], 1);
        g_src[p] = a; g_w[p] = w;
        int q = atomicAdd(&g_cur[a], 1);
        g_src[q] = b; g_w[q] = w;
    }
}

// ---------------- fp32 -> fp16 convert of the node table (layer 1 only) ----------
__global__ void k_cvt(const float* __restrict__ x) {
    int i = blockIdx.x * blockDim.x + threadIdx.x;
    const int N4 = NN * DM / 4;
    if (i < N4) {
        float4 v = __ldg(&((const float4*)x)[i]);
        ((__half2*)g_xh)[2 * i]     = __floats2half2_rn(v.x, v.y);
        ((__half2*)g_xh)[2 * i + 1] = __floats2half2_rn(v.z, v.w);
    }
}

// ---------------- W^T fp16 prep (once per layer) ----------------
__global__ void k_prepW(const float* __restrict__ W) {
    int i = blockIdx.x * blockDim.x + threadIdx.x;   // i = k*128 + n (coalesced read)
    if (i < DM * DM) {
        int n = i & 127, k = i >> 7;
        g_wt[n * DM + k] = __float2half_rn(W[i]);
    }
}

// ---------------- aggregation: warp/node, 2 edges per instruction, LDG.128 -------
// 16 lanes cover one 256B row (uint4/lane); half-warps process different edges.
__device__ __forceinline__ void acc8(float* f, float w, uint4 u) {
    __half2 h0 = *(__half2*)&u.x;
    __half2 h1 = *(__half2*)&u.y;
    __half2 h2 = *(__half2*)&u.z;
    __half2 h3 = *(__half2*)&u.w;
    float2 a0 = __half22float2(h0);
    float2 a1 = __half22float2(h1);
    float2 a2 = __half22float2(h2);
    float2 a3 = __half22float2(h3);
    f[0] = fmaf(w, a0.x, f[0]);
    f[1] = fmaf(w, a0.y, f[1]);
    f[2] = fmaf(w, a1.x, f[2]);
    f[3] = fmaf(w, a1.y, f[3]);
    f[4] = fmaf(w, a2.x, f[4]);
    f[5] = fmaf(w, a2.y, f[5]);
    f[6] = fmaf(w, a3.x, f[6]);
    f[7] = fmaf(w, a3.y, f[7]);
}

__global__ void k_agg() {
    int warp = (blockIdx.x * blockDim.x + threadIdx.x) >> 5;
    int lane = threadIdx.x & 31;
    if (warp >= NN) return;
    int h = lane >> 4;          // which edge slot this half-warp serves
    int sub = lane & 15;        // feature chunk: halves [8*sub, 8*sub+8)
    int beg = g_off[warp], end = g_off[warp + 1];

    float f[8];
#pragma unroll
    for (int q = 0; q < 8; q++) f[q] = 0.f;

    const uint4* __restrict__ x4 = (const uint4*)g_xh;   // row = 16 uint4

    int j = beg;
    // fast path: 8 edges / iteration (4 per half-warp), 4 gathers in flight per lane
    for (; j + 8 <= end; j += 8) {
        int   s0 = __ldg(&g_src[j + 0 + h]);
        int   s1 = __ldg(&g_src[j + 2 + h]);
        int   s2 = __ldg(&g_src[j + 4 + h]);
        int   s3 = __ldg(&g_src[j + 6 + h]);
        float w0 = __ldg(&g_w[j + 0 + h]);
        float w1 = __ldg(&g_w[j + 2 + h]);
        float w2 = __ldg(&g_w[j + 4 + h]);
        float w3 = __ldg(&g_w[j + 6 + h]);
        uint4 u0 = __ldg(&x4[(size_t)s0 * 16 + sub]);
        uint4 u1 = __ldg(&x4[(size_t)s1 * 16 + sub]);
        uint4 u2 = __ldg(&x4[(size_t)s2 * 16 + sub]);
        uint4 u3 = __ldg(&x4[(size_t)s3 * 16 + sub]);
        acc8(f, w0, u0);
        acc8(f, w1, u1);
        acc8(f, w2, u2);
        acc8(f, w3, u3);
    }
    // remainder (<=7 edges), masked but still batched
    if (j < end) {
        const uint4 z = make_uint4(0u, 0u, 0u, 0u);
#pragma unroll
        for (int i = 0; i < 4; i++) {
            int idx = j + 2 * i + h;
            bool v = idx < end;
            int   s = v ? __ldg(&g_src[idx]) : 0;
            float w = v ? __ldg(&g_w[idx]) : 0.f;
            uint4 u = v ? __ldg(&x4[(size_t)s * 16 + sub]) : z;
            acc8(f, w, u);
        }
    }

    // merge the two half-warps' partial sums
#pragma unroll
    for (int q = 0; q < 8; q++)
        f[q] += __shfl_xor_sync(0xffffffffu, f[q], 16);

    if (h == 0) {
        uint4 hv;
        hv.x = h2_to_u32(__floats2half2_rn(f[0], f[1]));
        hv.y = h2_to_u32(__floats2half2_rn(f[2], f[3]));
        hv.z = h2_to_u32(__floats2half2_rn(f[4], f[5]));
        hv.w = h2_to_u32(__floats2half2_rn(f[6], f[7]));
        ((uint4*)g_aggh)[(size_t)warp * 16 + sub] = hv;
    }
}

// ---------------- HMMA GEMM: out = res + g_aggh @ W + b --------------------------
// 128x128 tile per CTA, 8 warps; warp w -> rows [16w,16w+16), all 128 cols.
// A, B(W^T) fp16 in smem stride 136 halves (272B: conflict-free ldmatrix).
#define SAW 136

__global__ void __launch_bounds__(256)
k_gemm_mma(const float* __restrict__ bias, const float* __restrict__ res,
           float* __restrict__ out, int write_half) {
    extern __shared__ __half sh[];
    __half* sA = sh;                         // [128][SAW]
    __half* sB = sh + 128 * SAW;             // [128][SAW]  (W^T: [n][k])
    float* sBias = (float*)(sh + 2 * 128 * SAW);

    int tid = threadIdx.x;
    int w = tid >> 5, l = tid & 31;
    int rowBase = blockIdx.x * 128;

    if (tid < 128) sBias[tid] = __ldg(&bias[tid]);

    // load A tile from g_aggh (128 rows x 64 half2)
    const __half2* ag = (const __half2*)g_aggh;
#pragma unroll
    for (int i = 0; i < 32; i++) {
        int idx = tid + i * 256;             // 0..8191
        int row = idx >> 6;
        int kk = idx & 63;                   // half2 index along k
        int grow = rowBase + row;
        __half2 v = (grow < NN) ? __ldg(&ag[(size_t)grow * 64 + kk])
                                : __float2half2_rn(0.f);
        *(__half2*)&sA[row * SAW + kk * 2] = v;
    }
    // load B = W^T [n][k]
    const __half2* wt = (const __half2*)g_wt;
#pragma unroll
    for (int i = 0; i < 32; i++) {
        int idx = tid + i * 256;
        int n = idx >> 6;
        int kk = idx & 63;
        *(__half2*)&sB[n * SAW + kk * 2] = __ldg(&wt[idx]);
    }
    __syncthreads();

    uint32_t aBase = smem_to_u32(sA);
    uint32_t bBase = smem_to_u32(sB);

    float acc[16][4];
#pragma unroll
    for (int i = 0; i < 16; i++)
#pragma unroll
        for (int jj = 0; jj < 4; jj++) acc[i][jj] = 0.f;

    // lane address components (constant over k loop)
    int aRow = 16 * w + (l & 15);
    int aKsub = (l >> 4) * 8;                // 0 or 8
    int bNsub = ((l >> 4) & 1) * 8 + (l & 7);
    int bKsub = ((l >> 3) & 1) * 8;

#pragma unroll
    for (int s = 0; s < 8; s++) {
        uint32_t a[4];
        ldsm4(a, aBase + ((aRow * SAW + s * 16 + aKsub) << 1));
#pragma unroll
        for (int ntp = 0; ntp < 8; ntp++) {
            uint32_t b[4];
            int n = 16 * ntp + bNsub;
            ldsm4(b, bBase + ((n * SAW + s * 16 + bKsub) << 1));
            mma16816(acc[2 * ntp + 0], a, b);
            mma16816(acc[2 * ntp + 1], a, b + 2);
        }
    }

    // epilogue: + residual + bias; fp32 out (+ optional fp16 copy)
    int group = l >> 2, tg = l & 3;
#pragma unroll
    for (int hh = 0; hh < 2; hh++) {
        int grow = rowBase + 16 * w + group + hh * 8;
        if (grow < NN) {
            const float* rp = &res[(size_t)grow * DM];
            float* op = &out[(size_t)grow * DM];
            __half* hp = &g_xh[(size_t)grow * DM];
#pragma unroll
            for (int nt = 0; nt < 16; nt++) {
                int c = 8 * nt + 2 * tg;
                float2 rv = *(const float2*)&rp[c];
                float o0 = rv.x + acc[nt][hh * 2 + 0] + sBias[c];
                float o1 = rv.y + acc[nt][hh * 2 + 1] + sBias[c + 1];
                *(float2*)&op[c] = make_float2(o0, o1);
                if (write_half)
                    *(uint32_t*)&hp[c] = h2_to_u32(__floats2half2_rn(o0, o1));
            }
        }
    }
}

// ---------------- launch ----------------
extern "C" void kernel_launch(void* const* d_in, const int* in_sizes, int n_in,
                              void* d_out, int out_size) {
    const float* nodes     = (const float*)d_in[0];
    const int*   senders   = (const int*)d_in[1];
    const int*   receivers = (const int*)d_in[2];
    const float* edges     = (const float*)d_in[3];
    const float* W1 = (const float*)d_in[4];
    const float* b1 = (const float*)d_in[5];
    const float* W2 = (const float*)d_in[6];
    const float* b2 = (const float*)d_in[7];
    float* out = (float*)d_out;

    float* buf1 = nullptr;
    cudaGetSymbolAddress((void**)&buf1, g_buf1);

    const size_t SMEM_GEMM = 2 * 128 * SAW * sizeof(__half) + DM * sizeof(float);
    cudaFuncSetAttribute(k_gemm_mma, cudaFuncAttributeMaxDynamicSharedMemorySize,
                         (int)SMEM_GEMM);

    const int T = 256;
    // CSR + degree build (shared by both layers)
    k_zero<<<(NN + T - 1) / T, T>>>();
    k_deg<<<(NE + T - 1) / T, T>>>(senders, receivers, edges);
    k_dis<<<(NN + T - 1) / T, T>>>();
    k_scan1<<<SNB, SCB>>>();
    k_scan2<<<1, 512>>>();
    k_scan3<<<SNB, SCB>>>();
    k_fill<<<(NE + T - 1) / T, T>>>(senders, receivers, edges);

    const int AGG_GRID  = (NN * 32 + T - 1) / T;       // one warp per node
    const int GEMM_GRID = (NN + 127) / 128;            // 782 tiles
    const int CVT_GRID  = (NN * DM / 4 + T - 1) / T;

    // layer 1: nodes -> buf1 (gemm also emits fp16 copy for layer-2 gather)
    k_cvt<<<CVT_GRID, T>>>(nodes);
    k_prepW<<<(DM * DM + T - 1) / T, T>>>(W1);
    k_agg<<<AGG_GRID, T>>>();
    k_gemm_mma<<<GEMM_GRID, T, SMEM_GEMM>>>(b1, nodes, buf1, 1);

    // layer 2: buf1 -> out
    k_prepW<<<(DM * DM + T - 1) / T, T>>>(W2);
    k_agg<<<AGG_GRID, T>>>();
    k_gemm_mma<<<GEMM_GRID, T, SMEM_GEMM>>>(b2, buf1, out, 0);
}

// round 10
// speedup vs baseline: 1.1590x; 1.1590x over previous
#include <cuda_runtime.h>
#include <cuda_fp16.h>
#include <cuda_bf16.h>
#include <cstdint>
#include <cstring>

#define NN 100000
#define NE 800000
#define DM 128

typedef unsigned long long u64;

__device__ __forceinline__ uint32_t smem_to_u32(const void* p) {
    uint32_t a;
    asm("{ .reg .u64 t; cvta.to.shared.u64 t, %1; cvt.u32.u64 %0, t; }" : "=r"(a) : "l"(p));
    return a;
}
__device__ __forceinline__ uint32_t h2_to_u32(__half2 h) {
    uint32_t u;
    memcpy(&u, &h, 4);
    return u;
}
__device__ __forceinline__ void ldsm4(uint32_t* r, uint32_t addr) {
    asm volatile("ldmatrix.sync.aligned.m8n8.x4.shared.b16 {%0,%1,%2,%3}, [%4];"
        : "=r"(r[0]), "=r"(r[1]), "=r"(r[2]), "=r"(r[3]) : "r"(addr));
}
__device__ __forceinline__ void mma16816(float* c, const uint32_t* a, const uint32_t* b) {
    asm volatile(
        "mma.sync.aligned.m16n8k16.row.col.f32.f16.f16.f32 "
        "{%0,%1,%2,%3}, {%4,%5,%6,%7}, {%8,%9}, {%0,%1,%2,%3};"
        : "+f"(c[0]), "+f"(c[1]), "+f"(c[2]), "+f"(c[3])
        : "r"(a[0]), "r"(a[1]), "r"(a[2]), "r"(a[3]), "r"(b[0]), "r"(b[1]));
}

// ---------------- scratch (device globals: no cudaMalloc allowed) ----------------
__device__ float  g_deg[NN];
__device__ float  g_dis[NN];
__device__ int    g_cnt[NN];
__device__ int    g_off[NN + 1];
__device__ int    g_cur[NN];
__device__ uint2  g_ew[2 * NE];              // packed (src, w-bits) per directed edge
__device__ __half g_aggh[(size_t)NN * DM];   // aggregation result, fp16 (A of GEMM)
__device__ __half g_xh[(size_t)NN * DM];     // node features fp16 (gather + residual)
__device__ __half g_wt[DM * DM];             // W^T fp16, [n][k] row-major

#define SCB 256
#define SNB ((NN + SCB - 1) / SCB)   // 391 scan blocks
__device__ int g_bsum[SNB];
__device__ int g_boff[SNB];

// ---------------- build kernels ----------------
__global__ void k_zero() {
    int i = blockIdx.x * blockDim.x + threadIdx.x;
    if (i < NN) { g_deg[i] = 0.f; g_cnt[i] = 0; }
}

__global__ void k_deg(const int* __restrict__ s, const int* __restrict__ r,
                      const float* __restrict__ e) {
    int i = blockIdx.x * blockDim.x + threadIdx.x;
    if (i < NE) {
        int a = s[i], b = r[i];
        float ev = e[i];
        atomicAdd(&g_deg[a], ev);
        atomicAdd(&g_deg[b], ev);
        atomicAdd(&g_cnt[a], 1);
        atomicAdd(&g_cnt[b], 1);
    }
}

// scan1 also computes dis (merged former k_dis)
__global__ void k_scan1() {
    __shared__ int sh[SCB];
    int i = blockIdx.x * SCB + threadIdx.x;
    int v = 0;
    if (i < NN) {
        v = g_cnt[i];
        float d = g_deg[i];
        g_dis[i] = (d > 0.f) ? rsqrtf(d) : 0.f;
    }
    sh[threadIdx.x] = v;
    __syncthreads();
    for (int d = SCB / 2; d > 0; d >>= 1) {
        if (threadIdx.x < d) sh[threadIdx.x] += sh[threadIdx.x + d];
        __syncthreads();
    }
    if (threadIdx.x == 0) g_bsum[blockIdx.x] = sh[0];
}

__global__ void k_scan2() {
    __shared__ int sh[512];
    int t = threadIdx.x;
    int v = (t < SNB) ? g_bsum[t] : 0;
    sh[t] = v;
    __syncthreads();
    for (int d = 1; d < 512; d <<= 1) {
        int x = 0;
        if (t >= d) x = sh[t - d];
        __syncthreads();
        sh[t] += x;
        __syncthreads();
    }
    if (t < SNB) g_boff[t] = sh[t] - v;
    if (t == SNB - 1) g_off[NN] = sh[t];
}

__global__ void k_scan3() {
    __shared__ int sh[SCB];
    int i = blockIdx.x * SCB + threadIdx.x;
    int t = threadIdx.x;
    int v = (i < NN) ? g_cnt[i] : 0;
    sh[t] = v;
    __syncthreads();
    for (int d = 1; d < SCB; d <<= 1) {
        int x = 0;
        if (t >= d) x = sh[t - d];
        __syncthreads();
        sh[t] += x;
        __syncthreads();
    }
    if (i < NN) {
        int excl = sh[t] - v + g_boff[blockIdx.x];
        g_off[i] = excl;
        g_cur[i] = excl;
    }
}

__global__ void k_fill(const int* __restrict__ s, const int* __restrict__ r,
                       const float* __restrict__ e) {
    int i = blockIdx.x * blockDim.x + threadIdx.x;
    if (i < NE) {
        int a = s[i], b = r[i];
        float w = g_dis[a] * e[i] * g_dis[b];
        uint32_t wb = __float_as_uint(w);
        int p = atomicAdd(&g_cur[b], 1);       // edge a->b aggregated at b
        g_ew[p] = make_uint2((uint32_t)a, wb);
        int q = atomicAdd(&g_cur[a], 1);       // edge b->a aggregated at a
        g_ew[q] = make_uint2((uint32_t)b, wb);
    }
}

// ---------------- fp32 -> fp16 convert of the node table (layer 1 only) ----------
__global__ void k_cvt(const float* __restrict__ x) {
    int i = blockIdx.x * blockDim.x + threadIdx.x;
    const int N4 = NN * DM / 4;
    if (i < N4) {
        float4 v = __ldg(&((const float4*)x)[i]);
        ((__half2*)g_xh)[2 * i]     = __floats2half2_rn(v.x, v.y);
        ((__half2*)g_xh)[2 * i + 1] = __floats2half2_rn(v.z, v.w);
    }
}

// ---------------- W^T fp16 prep (once per layer) ----------------
__global__ void k_prepW(const float* __restrict__ W) {
    int i = blockIdx.x * blockDim.x + threadIdx.x;   // i = k*128 + n (coalesced read)
    if (i < DM * DM) {
        int n = i & 127, k = i >> 7;
        g_wt[n * DM + k] = __float2half_rn(W[i]);
    }
}

// ---------------- aggregation: one warp per node, fp16 gather, MLP=4 -------------
__device__ __forceinline__ void acc_edge(float4& acc, float w, uint2 u) {
    __half2 h0 = *(__half2*)&u.x;
    __half2 h1 = *(__half2*)&u.y;
    float2 f0 = __half22float2(h0);
    float2 f1 = __half22float2(h1);
    acc.x = fmaf(w, f0.x, acc.x);
    acc.y = fmaf(w, f0.y, acc.y);
    acc.z = fmaf(w, f1.x, acc.z);
    acc.w = fmaf(w, f1.y, acc.w);
}

__global__ void k_agg() {
    int warp = (blockIdx.x * blockDim.x + threadIdx.x) >> 5;
    int lane = threadIdx.x & 31;
    if (warp >= NN) return;
    int beg = g_off[warp], end = g_off[warp + 1];
    float4 acc = make_float4(0.f, 0.f, 0.f, 0.f);
    const uint2* __restrict__ xh2 = (const uint2*)g_xh;

    int j = beg;
    for (; j + 4 <= end; j += 4) {
        uint2 e0 = __ldg(&g_ew[j + 0]);
        uint2 e1 = __ldg(&g_ew[j + 1]);
        uint2 e2 = __ldg(&g_ew[j + 2]);
        uint2 e3 = __ldg(&g_ew[j + 3]);
        uint2 u0 = __ldg(&xh2[(size_t)e0.x * 32 + lane]);
        uint2 u1 = __ldg(&xh2[(size_t)e1.x * 32 + lane]);
        uint2 u2 = __ldg(&xh2[(size_t)e2.x * 32 + lane]);
        uint2 u3 = __ldg(&xh2[(size_t)e3.x * 32 + lane]);
        acc_edge(acc, __uint_as_float(e0.y), u0);
        acc_edge(acc, __uint_as_float(e1.y), u1);
        acc_edge(acc, __uint_as_float(e2.y), u2);
        acc_edge(acc, __uint_as_float(e3.y), u3);
    }
    {
        int rem = end - j;
        uint2 ez = make_uint2(0u, 0u);
        uint2 e0 = (rem > 0) ? __ldg(&g_ew[j + 0]) : ez;
        uint2 e1 = (rem > 1) ? __ldg(&g_ew[j + 1]) : ez;
        uint2 e2 = (rem > 2) ? __ldg(&g_ew[j + 2]) : ez;
        uint2 z = make_uint2(0u, 0u);
        uint2 u0 = (rem > 0) ? __ldg(&xh2[(size_t)e0.x * 32 + lane]) : z;
        uint2 u1 = (rem > 1) ? __ldg(&xh2[(size_t)e1.x * 32 + lane]) : z;
        uint2 u2 = (rem > 2) ? __ldg(&xh2[(size_t)e2.x * 32 + lane]) : z;
        acc_edge(acc, (rem > 0) ? __uint_as_float(e0.y) : 0.f, u0);
        acc_edge(acc, (rem > 1) ? __uint_as_float(e1.y) : 0.f, u1);
        acc_edge(acc, (rem > 2) ? __uint_as_float(e2.y) : 0.f, u2);
    }
    // write fp16 (A operand of the HMMA GEMM)
    uint2 hv;
    hv.x = h2_to_u32(__floats2half2_rn(acc.x, acc.y));
    hv.y = h2_to_u32(__floats2half2_rn(acc.z, acc.w));
    ((uint2*)g_aggh)[(size_t)warp * 32 + lane] = hv;
}

// ---------------- HMMA GEMM ------------------------------------------------------
// mode 1 (layer 1): out_h(g_xh) = resf(fp32) + A@W + b        (writes fp16 only)
// mode 2 (layer 2): out(fp32)   = g_xh(fp16 residual) + A@W + b
// 128x128 tile per CTA, 8 warps; warp w -> rows [16w,16w+16), all 128 cols.
#define SAW 136

__global__ void __launch_bounds__(256)
k_gemm_mma(const float* __restrict__ bias, const float* __restrict__ resf,
           float* __restrict__ out, int mode) {
    extern __shared__ __half sh[];
    __half* sA = sh;                         // [128][SAW]
    __half* sB = sh + 128 * SAW;             // [128][SAW]  (W^T: [n][k])
    float* sBias = (float*)(sh + 2 * 128 * SAW);

    int tid = threadIdx.x;
    int w = tid >> 5, l = tid & 31;
    int rowBase = blockIdx.x * 128;

    if (tid < 128) sBias[tid] = __ldg(&bias[tid]);

    // load A tile from g_aggh (128 rows x 64 half2)
    const __half2* ag = (const __half2*)g_aggh;
#pragma unroll
    for (int i = 0; i < 32; i++) {
        int idx = tid + i * 256;             // 0..8191
        int row = idx >> 6;
        int kk = idx & 63;                   // half2 index along k
        int grow = rowBase + row;
        __half2 v = (grow < NN) ? __ldg(&ag[(size_t)grow * 64 + kk])
                                : __float2half2_rn(0.f);
        *(__half2*)&sA[row * SAW + kk * 2] = v;
    }
    // load B = W^T [n][k]
    const __half2* wt = (const __half2*)g_wt;
#pragma unroll
    for (int i = 0; i < 32; i++) {
        int idx = tid + i * 256;
        int n = idx >> 6;
        int kk = idx & 63;
        *(__half2*)&sB[n * SAW + kk * 2] = __ldg(&wt[idx]);
    }
    __syncthreads();

    uint32_t aBase = smem_to_u32(sA);
    uint32_t bBase = smem_to_u32(sB);

    float acc[16][4];
#pragma unroll
    for (int i = 0; i < 16; i++)
#pragma unroll
        for (int jj = 0; jj < 4; jj++) acc[i][jj] = 0.f;

    int aRow = 16 * w + (l & 15);
    int aKsub = (l >> 4) * 8;
    int bNsub = ((l >> 4) & 1) * 8 + (l & 7);
    int bKsub = ((l >> 3) & 1) * 8;

#pragma unroll
    for (int s = 0; s < 8; s++) {
        uint32_t a[4];
        ldsm4(a, aBase + ((aRow * SAW + s * 16 + aKsub) << 1));
#pragma unroll
        for (int ntp = 0; ntp < 8; ntp++) {
            uint32_t b[4];
            int n = 16 * ntp + bNsub;
            ldsm4(b, bBase + ((n * SAW + s * 16 + bKsub) << 1));
            mma16816(acc[2 * ntp + 0], a, b);
            mma16816(acc[2 * ntp + 1], a, b + 2);
        }
    }

    // epilogue
    int group = l >> 2, tg = l & 3;
#pragma unroll
    for (int hh = 0; hh < 2; hh++) {
        int grow = rowBase + 16 * w + group + hh * 8;
        if (grow < NN) {
            if (mode == 1) {
                const float* rp = &resf[(size_t)grow * DM];
                __half* hp = &g_xh[(size_t)grow * DM];
#pragma unroll
                for (int nt = 0; nt < 16; nt++) {
                    int c = 8 * nt + 2 * tg;
                    float2 rv = *(const float2*)&rp[c];
                    float o0 = rv.x + acc[nt][hh * 2 + 0] + sBias[c];
                    float o1 = rv.y + acc[nt][hh * 2 + 1] + sBias[c + 1];
                    *(uint32_t*)&hp[c] = h2_to_u32(__floats2half2_rn(o0, o1));
                }
            } else {
                const __half* rh = &g_xh[(size_t)grow * DM];
                float* op = &out[(size_t)grow * DM];
#pragma unroll
                for (int nt = 0; nt < 16; nt++) {
                    int c = 8 * nt + 2 * tg;
                    __half2 rv2 = *(const __half2*)&rh[c];
                    float2 rv = __half22float2(rv2);
                    float o0 = rv.x + acc[nt][hh * 2 + 0] + sBias[c];
                    float o1 = rv.y + acc[nt][hh * 2 + 1] + sBias[c + 1];
                    *(float2*)&op[c] = make_float2(o0, o1);
                }
            }
        }
    }
}

// ---------------- launch ----------------
extern "C" void kernel_launch(void* const* d_in, const int* in_sizes, int n_in,
                              void* d_out, int out_size) {
    const float* nodes     = (const float*)d_in[0];
    const int*   senders   = (const int*)d_in[1];
    const int*   receivers = (const int*)d_in[2];
    const float* edges     = (const float*)d_in[3];
    const float* W1 = (const float*)d_in[4];
    const float* b1 = (const float*)d_in[5];
    const float* W2 = (const float*)d_in[6];
    const float* b2 = (const float*)d_in[7];
    float* out = (float*)d_out;

    const size_t SMEM_GEMM = 2 * 128 * SAW * sizeof(__half) + DM * sizeof(float);
    cudaFuncSetAttribute(k_gemm_mma, cudaFuncAttributeMaxDynamicSharedMemorySize,
                         (int)SMEM_GEMM);

    const int T = 256;
    // CSR + degree build (shared by both layers)
    k_zero<<<(NN + T - 1) / T, T>>>();
    k_deg<<<(NE + T - 1) / T, T>>>(senders, receivers, edges);
    k_scan1<<<SNB, SCB>>>();           // also computes g_dis
    k_scan2<<<1, 512>>>();
    k_scan3<<<SNB, SCB>>>();
    k_fill<<<(NE + T - 1) / T, T>>>(senders, receivers, edges);

    const int AGG_GRID  = (NN * 32 + T - 1) / T;       // one warp per node
    const int GEMM_GRID = (NN + 127) / 128;            // 782 tiles
    const int CVT_GRID  = (NN * DM / 4 + T - 1) / T;

    // layer 1: nodes -> g_xh (fp16 only)
    k_cvt<<<CVT_GRID, T>>>(nodes);
    k_prepW<<<(DM * DM + T - 1) / T, T>>>(W1);
    k_agg<<<AGG_GRID, T>>>();
    k_gemm_mma<<<GEMM_GRID, T, SMEM_GEMM>>>(b1, nodes, nullptr, 1);

    // layer 2: g_xh -> out (fp32)
    k_prepW<<<(DM * DM + T - 1) / T, T>>>(W2);
    k_agg<<<AGG_GRID, T>>>();
    k_gemm_mma<<<GEMM_GRID, T, SMEM_GEMM>>>(b2, nullptr, out, 2);
}